// round 14
// baseline (speedup 1.0000x reference)
#include <cuda_runtime.h>
#include <cuda_fp16.h>
#include <cstdint>

// ============================================================================
// GroupWiseLinearProjector, single-pass fp16 mma.sync GEMM (compute_103)
//   out[b,o,h,w] = sum_c x[b,c,h,w] * Wg[p(h,w),o,c],  p=(h%4)*4+(w%4)
// R14: warp owns all 4 q of a 32o x 16px patch -> epilogue is 16 direct
//   STG.128 from registers (no smem staging, no epilogue syncs).
//   Persistent CTAs (grid=148, ~7 tiles each), cp.async pipeline flows
//   across tile boundaries (prologue paid once).
// ============================================================================

#define B_   16
#define CIN  512
#define COUT 512
#define NPX  256
#define KC   64          // K chunk (64 fp16 = 128B row, SW128 swizzle)
#define NSTAGE 8         // 512 / 64
#define NTILES_TOTAL 1024
#define GRID_CTAS 148

// ---------------- scratch (device globals; no allocation) ----------------
__device__ __align__(256) unsigned short g_Xh[B_ * 16 * NPX * CIN];    // 64MB
__device__ __align__(256) unsigned short g_Wh[16 * COUT * CIN];        // 8MB

// ---------------- helpers ----------------
__device__ __forceinline__ uint32_t smem_to_u32(const void* p) {
    uint32_t a;
    asm("{ .reg .u64 t; cvta.to.shared.u64 t, %1; cvt.u32.u64 %0, t; }"
        : "=r"(a) : "l"(p));
    return a;
}
__device__ __forceinline__ void cp_async16(uint32_t dst, const void* src) {
    asm volatile("cp.async.cg.shared.global [%0], [%1], 16;"
                 :: "r"(dst), "l"(src) : "memory");
}
#define CP_COMMIT() asm volatile("cp.async.commit_group;" ::: "memory")
#define CP_WAIT(n)  asm volatile("cp.async.wait_group %0;" :: "n"(n) : "memory")

__device__ __forceinline__ void ldmx4(uint32_t* r, uint32_t addr) {
    asm volatile("ldmatrix.sync.aligned.m8n8.x4.shared.b16 {%0,%1,%2,%3}, [%4];"
                 : "=r"(r[0]), "=r"(r[1]), "=r"(r[2]), "=r"(r[3]) : "r"(addr));
}
__device__ __forceinline__ void mma16816(float* d, const uint32_t* a,
                                         uint32_t b0, uint32_t b1) {
    asm volatile(
        "mma.sync.aligned.m16n8k16.row.col.f32.f16.f16.f32 "
        "{%0,%1,%2,%3}, {%4,%5,%6,%7}, {%8,%9}, {%0,%1,%2,%3};"
        : "+f"(d[0]), "+f"(d[1]), "+f"(d[2]), "+f"(d[3])
        : "r"(a[0]), "r"(a[1]), "r"(a[2]), "r"(a[3]), "r"(b0), "r"(b1));
}
#define SWZ(off) ((uint32_t)(off) ^ ((((uint32_t)(off)) >> 3) & 0x70))

// ============================================================================
// Pass 1 (merged): blocks [0,2048) convert W; [2048,10240) convert x.
// ============================================================================
__global__ __launch_bounds__(256)
void convert_kernel(const float* __restrict__ Wg, const float* __restrict__ x) {
    if (blockIdx.x < 2048) {
        size_t gt = (size_t)blockIdx.x * 256 + threadIdx.x;
        const float4* src = reinterpret_cast<const float4*>(Wg) + gt * 2;
        float4 a = src[0], b = src[1];
        float v[8] = {a.x, a.y, a.z, a.w, b.x, b.y, b.z, b.w};
        unsigned short hb[8];
#pragma unroll
        for (int i = 0; i < 8; i++)
            hb[i] = __half_as_ushort(__float2half_rn(v[i]));
        uint4 uh;
        uh.x = hb[0] | (uint32_t)hb[1] << 16;  uh.y = hb[2] | (uint32_t)hb[3] << 16;
        uh.z = hb[4] | (uint32_t)hb[5] << 16;  uh.w = hb[6] | (uint32_t)hb[7] << 16;
        *reinterpret_cast<uint4*>(g_Wh + gt * 8) = uh;
        return;
    }
    __shared__ float sin[64][68];
    int bid = blockIdx.x - 2048;          // 16 * 64 * 8 = 8192
    int cc = bid & 7;
    int h  = (bid >> 3) & 63;
    int b  = bid >> 9;
    int c0 = cc * 64;
    int t  = threadIdx.x;

    const float* src = x + (((size_t)b * CIN + c0) * 64 + h) * 64;
    {
        int c  = t >> 2;
        int f0 = t & 3;
#pragma unroll
        for (int j = 0; j < 4; j++) {
            float4 v = *reinterpret_cast<const float4*>(src + (size_t)c * 4096 + (f0 + 4 * j) * 4);
            *reinterpret_cast<float4*>(&sin[c][(f0 + 4 * j) * 4]) = v;
        }
    }
    __syncthreads();

    int p   = t >> 2;
    int q   = p >> 4;
    int w4  = p & 15;
    int cc4 = t & 3;
    int r   = h & 3;
    int h4  = h >> 2;

    unsigned short hb[16];
#pragma unroll
    for (int i = 0; i < 16; i++)
        hb[i] = __half_as_ushort(__float2half_rn(sin[cc4 * 16 + i][q + 4 * w4]));

    int phase = r * 4 + q;
    int px    = h4 * 16 + w4;
    size_t off = (((size_t)(b * 16 + phase) * NPX) + px) * CIN + c0 + cc4 * 16;

    uint4 u0, u1;
    u0.x = hb[0] | (uint32_t)hb[1] << 16;   u0.y = hb[2]  | (uint32_t)hb[3] << 16;
    u0.z = hb[4] | (uint32_t)hb[5] << 16;   u0.w = hb[6]  | (uint32_t)hb[7] << 16;
    u1.x = hb[8] | (uint32_t)hb[9] << 16;   u1.y = hb[10] | (uint32_t)hb[11] << 16;
    u1.z = hb[12]| (uint32_t)hb[13] << 16;  u1.w = hb[14] | (uint32_t)hb[15] << 16;
    *reinterpret_cast<uint4*>(g_Xh + off)     = u0;
    *reinterpret_cast<uint4*>(g_Xh + off + 8) = u1;
}

// ============================================================================
// Pass 2: persistent fused GEMM.
//   Tile t = (b, r, otile 128o, ht 64px): 4 sub-GEMMs (q), K=512.
//   512 threads; warp = (oq = wid&3 -> 32 o, pq = wid>>2 -> 16 px), all 4 q.
//   Stage (96KB): W[q] 4x16KB | X[q] 4x8KB; double-buffered = 192KB.
//   Epilogue: 16 x STG.128 straight from accumulators.
// ============================================================================
#define STAGE_BYTES 98304
#define XOFF 65536

__global__ __launch_bounds__(512, 1)
void gwlp_mma_kernel(float* __restrict__ out) {
    extern __shared__ __align__(1024) char sm[];
    const uint32_t smb = smem_to_u32(sm);

    const int t   = threadIdx.x;
    const int wid = t >> 5;
    const int lid = t & 31;
    const int oq  = wid & 3;    // o quarter (32 rows)
    const int pq  = wid >> 2;   // px quarter (16 rows) == h4l

    const int cid    = blockIdx.x;                    // 148 persistent CTAs
    const int ntiles = (cid < (NTILES_TOTAL - 6 * GRID_CTAS)) ? 7 : 6; // 136x7+12x6
    const int gstot  = ntiles * NSTAGE;

    // ---- stage loader for global stage index gs ----
    auto load_gs = [&](int gs) {
        const int tile = cid + GRID_CTAS * (gs >> 3);
        const int ck   = gs & 7;
        const int ht    = tile & 3;
        const int otile = (tile >> 2) & 3;
        const int r     = (tile >> 4) & 3;
        const int b     = tile >> 6;
        const unsigned short* whp0 = g_Wh + ((size_t)(r * 4) * COUT + otile * 128) * CIN;
        const unsigned short* xhp0 = g_Xh + ((size_t)(b * 16 + r * 4) * NPX + ht * 64) * CIN;
        const uint32_t sb = smb + (uint32_t)(gs & 1) * STAGE_BYTES;
        const int ce = ck * KC;
#pragma unroll
        for (int i = 0; i < 8; i++) {      // W: 4096 granules (4q x 128 x 8)
            int gi  = t + i * 512;
            int lq  = gi >> 10;
            int wi  = gi & 1023;
            int row = wi >> 3, g = wi & 7;
            uint32_t d = sb + lq * 16384 + SWZ(row * 128 + g * 16);
            cp_async16(d, whp0 + (size_t)lq * (COUT * CIN) + (size_t)row * CIN + ce + g * 8);
        }
#pragma unroll
        for (int i = 0; i < 4; i++) {      // X: 2048 granules (4q x 64 x 8)
            int gi  = t + i * 512;
            int lq  = gi >> 9;
            int wi  = gi & 511;
            int row = wi >> 3, g = wi & 7;
            uint32_t d = sb + XOFF + lq * 8192 + SWZ(row * 128 + g * 16);
            cp_async16(d, xhp0 + (size_t)lq * (NPX * CIN) + (size_t)row * CIN + ce + g * 8);
        }
        CP_COMMIT();
    };

    // ---- per-lane ldmatrix address components ----
    const int lr = lid & 15;
    const int cb = lid >> 4;
    uint32_t a_off[2], a_key[2];
#pragma unroll
    for (int mt = 0; mt < 2; mt++) {
        int row = oq * 32 + mt * 16 + lr;
        a_off[mt] = (uint32_t)row * 128;
        a_key[mt] = (uint32_t)(row & 7) << 4;
    }
    uint32_t b_off, b_key;
    {
        int row = pq * 16 + lr;             // px rows pq*16 .. +15
        b_off = (uint32_t)row * 128;
        b_key = (uint32_t)(row & 7) << 4;
    }

    float acc[4][2][2][4];                  // [q][mt][nt][e]
#pragma unroll
    for (int q = 0; q < 4; q++)
#pragma unroll
        for (int mt = 0; mt < 2; mt++)
#pragma unroll
            for (int nt = 0; nt < 2; nt++)
#pragma unroll
                for (int e = 0; e < 4; e++)
                    acc[q][mt][nt][e] = 0.0f;

    const int g  = lid >> 2;
    const int tq = lid & 3;

    // ---- persistent pipeline ----
    load_gs(0);
    load_gs(1);

#pragma unroll 1
    for (int gs = 0; gs < gstot; gs++) {
        if (gs == gstot - 1) { CP_WAIT(0); } else { CP_WAIT(1); }
        __syncthreads();

        const uint32_t sb = smb + (uint32_t)(gs & 1) * STAGE_BYTES;
#pragma unroll
        for (int ks = 0; ks < 4; ks++) {
            const uint32_t col = (uint32_t)(ks * 32 + cb * 16);
            uint32_t bh[4][4];
#pragma unroll
            for (int q = 0; q < 4; q++)
                ldmx4(bh[q], sb + XOFF + (uint32_t)q * 8192 + b_off + (col ^ b_key));
#pragma unroll
            for (int q = 0; q < 4; q++) {
#pragma unroll
                for (int mt = 0; mt < 2; mt++) {
                    uint32_t ah[4];
                    ldmx4(ah, sb + (uint32_t)q * 16384 + a_off[mt] + (col ^ a_key[mt]));
                    mma16816(acc[q][mt][0], ah, bh[q][0], bh[q][2]);
                    mma16816(acc[q][mt][1], ah, bh[q][1], bh[q][3]);
                }
            }
        }

        // ---- tile finished? store directly from registers ----
        if ((gs & 7) == 7) {
            const int tile  = cid + GRID_CTAS * (gs >> 3);
            const int ht    = tile & 3;
            const int otile = (tile >> 2) & 3;
            const int r     = (tile >> 4) & 3;
            const int b     = tile >> 6;
            const int h     = 16 * ht + 4 * pq + r;
            float* obase = out + (((size_t)b * COUT + otile * 128 + oq * 32) * 64 + h) * 64;
#pragma unroll
            for (int mt = 0; mt < 2; mt++) {
#pragma unroll
                for (int nt = 0; nt < 2; nt++) {
#pragma unroll
                    for (int oh = 0; oh < 2; oh++) {
                        int oo = mt * 16 + g + oh * 8;
                        int px = nt * 8 + tq * 2;
                        float4 v0 = make_float4(acc[0][mt][nt][oh * 2],
                                                acc[1][mt][nt][oh * 2],
                                                acc[2][mt][nt][oh * 2],
                                                acc[3][mt][nt][oh * 2]);
                        float4 v1 = make_float4(acc[0][mt][nt][oh * 2 + 1],
                                                acc[1][mt][nt][oh * 2 + 1],
                                                acc[2][mt][nt][oh * 2 + 1],
                                                acc[3][mt][nt][oh * 2 + 1]);
                        *reinterpret_cast<float4*>(obase + (size_t)oo * 4096 + 4 * px)       = v0;
                        *reinterpret_cast<float4*>(obase + (size_t)oo * 4096 + 4 * (px + 1)) = v1;
                    }
                }
            }
            // reset accumulators for next tile
#pragma unroll
            for (int q = 0; q < 4; q++)
#pragma unroll
                for (int mt = 0; mt < 2; mt++)
#pragma unroll
                    for (int nt = 0; nt < 2; nt++)
#pragma unroll
                        for (int e = 0; e < 4; e++)
                            acc[q][mt][nt][e] = 0.0f;
        }

        __syncthreads();
        if (gs + 2 < gstot) load_gs(gs + 2);
    }
}

// ============================================================================
extern "C" void kernel_launch(void* const* d_in, const int* in_sizes, int n_in,
                              void* d_out, int out_size)
{
    const float* x  = (const float*)d_in[0];   // [16, 512, 64, 64]
    const float* Wg = (const float*)d_in[1];   // [16, 512, 512]
    float* out = (float*)d_out;                // [16, 512, 64, 64]

    cudaFuncSetAttribute(gwlp_mma_kernel,
                         cudaFuncAttributeMaxDynamicSharedMemorySize, 2 * STAGE_BYTES);

    convert_kernel<<<10240, 256>>>(Wg, x);
    gwlp_mma_kernel<<<GRID_CTAS, 512, 2 * STAGE_BYTES>>>(out);
}